// round 6
// baseline (speedup 1.0000x reference)
#include <cuda_runtime.h>
#include <cuda_bf16.h>

// Global scratch (zero-initialized at module load; reset by the last block
// every launch so each graph replay starts clean).
__device__ double        g_acc;
__device__ unsigned int  g_count;

// Persistent single-wave grid (148 SMs x 4 blocks), grid-stride over chunks
// of 512 float4 (2 float4 per thread per iteration).
//
// Element-parallel formulation. Key identity: every rewrite sets t <- p, so
// the per-element diff is
//   col 0/2: z = (p<0.1 && t==0) || (p>0.9 && t==1)       -> d = z ? 0 : p-t
//   col 1  : z = (p_next>0.9) || (1.02p > t && 0.98p < t) -> d = z ? 0 : p-t
// The only cross-element need is p[e+1] for col-1 elements, via __shfl_down
// (lane 31 patches the warp boundary with one predicated scalar load).
__global__ void __launch_bounds__(256) range_loss_kernel(
    const float4* __restrict__ preds4,
    const float4* __restrict__ target4,
    const float*  __restrict__ preds_flat,
    float* __restrict__ out,
    double inv_count,
    unsigned int nblocks,
    unsigned int n_chunks,     // total chunks of 512 float4
    unsigned int last_elem)    // nelem - 1
{
    const int lane = threadIdx.x & 31;
    const int wid  = threadIdx.x >> 5;

    float acc = 0.0f;

    for (unsigned c = blockIdx.x; c < n_chunks; c += nblocks) {
        const unsigned base = c * 512u + threadIdx.x;   // float4 index

        // 4 front-batched, fully coalesced LDG.128 (evict-first: single touch).
        float4 pv[2], tv[2];
        pv[0] = __ldcs(&preds4[base]);
        pv[1] = __ldcs(&preds4[base + 256u]);
        tv[0] = __ldcs(&target4[base]);
        tv[1] = __ldcs(&target4[base + 256u]);

        // Neighbor value p[4g+4] per float4 (needed when element j=3 is col-1).
        float nx[2];
        #pragma unroll
        for (int k = 0; k < 2; k++) {
            float v = __shfl_down_sync(0xffffffffu, pv[k].x, 1);
            if (lane == 31) {
                unsigned g   = base + 256u * k;
                unsigned idx = 4u * (g + 1u);
                if (idx > last_elem) idx = last_elem;  // clamp; value unused
                v = preds_flat[idx];
            }
            nx[k] = v;
        }

        #pragma unroll
        for (int k = 0; k < 2; k++) {
            const unsigned g = base + 256u * k;
            const unsigned r = g % 3u;   // col of element 4g is (4g)%3 = g%3

            float pe[4] = { pv[k].x, pv[k].y, pv[k].z, pv[k].w };
            float te[4] = { tv[k].x, tv[k].y, tv[k].z, tv[k].w };
            float pn[4] = { pv[k].y, pv[k].z, pv[k].w, nx[k] };

            #pragma unroll
            for (int j = 0; j < 4; j++) {
                // col of element 4g+j = (r + j) % 3 -> is it col 1?
                bool is1;
                if      (j == 0) is1 = (r == 1u);
                else if (j == 1) is1 = (r == 0u);
                else if (j == 2) is1 = (r == 2u);
                else             is1 = (r == 1u);

                float p = pe[j], t = te[j];
                bool z02 = (p < 0.1f && t == 0.0f) || (p > 0.9f && t == 1.0f);
                // 1.0+RANGE / 1.0-RANGE round to exactly 1.02f/0.98f in fp32.
                bool zin = (p * 1.02f > t) && (p * 0.98f < t);
                bool z1  = (pn[j] > 0.9f) || zin;
                bool z   = is1 ? z1 : z02;
                float d  = z ? 0.0f : (p - t);
                acc += d * d;
            }
        }
    }

    // Warp reduction
    #pragma unroll
    for (int o = 16; o > 0; o >>= 1)
        acc += __shfl_xor_sync(0xffffffffu, acc, o);

    // Cross-warp reduction in shared memory
    __shared__ float warp_sums[8];
    if (lane == 0) warp_sums[wid] = acc;
    __syncthreads();

    if (wid == 0) {
        float v = (lane < 8) ? warp_sums[lane] : 0.0f;
        #pragma unroll
        for (int o = 4; o > 0; o >>= 1)
            v += __shfl_xor_sync(0xffffffffu, v, o);

        if (lane == 0) {
            atomicAdd(&g_acc, (double)v);
            __threadfence();
            unsigned int done = atomicAdd(&g_count, 1u);
            if (done == nblocks - 1u) {
                // Last block: read+reset accumulator atomically, write result,
                // reset counter for the next replay.
                unsigned long long raw =
                    atomicExch((unsigned long long*)&g_acc, 0ull);
                double total = __longlong_as_double(raw);
                out[0] = (float)(total * inv_count);
                atomicExch(&g_count, 0u);
            }
        }
    }
}

extern "C" void kernel_launch(void* const* d_in, const int* in_sizes, int n_in,
                              void* d_out, int out_size)
{
    const float4* preds4     = (const float4*)d_in[0];
    const float4* target4    = (const float4*)d_in[1];
    const float*  preds_flat = (const float*)d_in[0];
    float* out = (float*)d_out;

    const long long nelem = (long long)in_sizes[0];   // N*3 = 25165824
    const long long nf4   = nelem / 4;                // 6291456 float4
    const unsigned int n_chunks = (unsigned int)(nf4 / 512);  // 12288

    // One wave: 148 SMs x 4 co-resident 256-thread blocks.
    const unsigned int grid = 148u * 4u;

    range_loss_kernel<<<grid, 256>>>(preds4, target4, preds_flat, out,
                                     1.0 / (double)nelem, grid, n_chunks,
                                     (unsigned int)(nelem - 1));
}